// round 9
// baseline (speedup 1.0000x reference)
#include <cuda_runtime.h>
#include <cuda_bf16.h>
#include <math.h>

// ---------------------------------------------------------------------------
// Attention4D: B=32, DIM=384, R=28 (N=784), H=8, KD=32, D=128, DH=1024
// Pipeline:
//   0. pack:   Wqkv -> d_Wpack[1536x384], affine (alpha,beta), abmix = th1 @ ab
//   1. gemm_nn: qkv[b] = Wpack @ x[b]  (epilogue: *alpha + beta)     [32x1536x784]
//   2. dwconv:  vl = affine(dw3x3(v) + bvl)                          [32x1024x784]
//   3. sumv:    sumV[b,ch] = sum_m v[b,ch,m]
//   4. logits:  L[b,g,n,m] = sum_h th1[g,h]*SCALE*(q_h . k_h) + abmix[g,idx] + th1_b[g]
//   5. softmax_mix: per (b,n): softmax over m per head, then th2 8x8 mix, in place
//   6. gemm_av: o[b,g*128+d,n] = sum_m attn2 * v  (+ th2_b*sumV + vl, ReLU)
//   7. gemm_nn: out[b] = Wp @ o[b]  (epilogue: *alphaP + betaP)
// ---------------------------------------------------------------------------

#define NB    32
#define CDIM  384
#define RR    28
#define NTOK  784          // 28*28
#define HH    8
#define KDHD  32
#define DDIM  128
#define DH    1024
#define QKVOC 1536
#define SCALE 0.17677669529663689f   // 32^-0.5

// ------------------------- scratch (device globals) -------------------------
__device__ float d_Wpack [QKVOC * CDIM];
__device__ float d_alpha1[QKVOC];
__device__ float d_beta1 [QKVOC];
__device__ float d_alphaP[CDIM];
__device__ float d_betaP [CDIM];
__device__ float d_abmix [HH * NTOK];
__device__ float d_qkv [(long long)NB * QKVOC * NTOK];       // 154 MB
__device__ float d_L   [(long long)NB * HH * NTOK * NTOK];   // 629 MB
__device__ float d_vl  [(long long)NB * DH * NTOK];          // 103 MB
__device__ float d_obuf[(long long)NB * DH * NTOK];          // 103 MB
__device__ float d_sumV[NB * DH];

// ------------------------------ 0: pack ------------------------------------
__global__ void pack_params(const float* __restrict__ Wq, const float* __restrict__ bq,
                            const float* __restrict__ sq, const float* __restrict__ tq,
                            const float* __restrict__ Wk, const float* __restrict__ bk,
                            const float* __restrict__ sk, const float* __restrict__ tk,
                            const float* __restrict__ Wv, const float* __restrict__ bv,
                            const float* __restrict__ sv, const float* __restrict__ tv,
                            const float* __restrict__ bp, const float* __restrict__ sp,
                            const float* __restrict__ tp,
                            const float* __restrict__ th1w, const float* __restrict__ ab)
{
    int idx = blockIdx.x * 256 + threadIdx.x;
    if (idx < QKVOC * CDIM) {
        int row = idx / CDIM, col = idx - row * CDIM;
        float w;
        if (row < 256)      w = Wq[row * CDIM + col];
        else if (row < 512) w = Wk[(row - 256) * CDIM + col];
        else                w = Wv[(row - 512) * CDIM + col];
        d_Wpack[idx] = w;
    }
    if (idx < QKVOC) {
        float s, b0, t;
        if (idx < 256)      { s = sq[idx];       b0 = bq[idx];       t = tq[idx]; }
        else if (idx < 512) { int r = idx - 256; s = sk[r]; b0 = bk[r]; t = tk[r]; }
        else                { int r = idx - 512; s = sv[r]; b0 = bv[r]; t = tv[r]; }
        d_alpha1[idx] = s;
        d_beta1[idx]  = b0 * s + t;
    }
    if (idx < CDIM) {
        d_alphaP[idx] = sp[idx];
        d_betaP[idx]  = bp[idx] * sp[idx] + tp[idx];
    }
    if (idx < HH * NTOK) {
        int g = idx / NTOK, p = idx - g * NTOK;
        float acc = 0.f;
        #pragma unroll
        for (int h = 0; h < HH; h++) acc += th1w[g * HH + h] * ab[h * NTOK + p];
        d_abmix[idx] = acc;
    }
}

// ------------------------- generic NN SGEMM + affine ------------------------
// C[b] = A @ B[b], A row-major [M,K], B row-major [K,Ncols]. M%64==0, K%16==0.
__global__ void __launch_bounds__(256) gemm_nn_affine(
    const float* __restrict__ A, const float* __restrict__ B, long long strideB,
    float* __restrict__ C, long long strideC,
    const float* __restrict__ alpha, const float* __restrict__ beta,
    int M, int Ncols, int K)
{
    __shared__ float As[16][68];
    __shared__ float Bs[16][64];
    int tid = threadIdx.x;
    int b   = blockIdx.z;
    const float* Bp = B + (long long)b * strideB;
    float*       Cp = C + (long long)b * strideC;
    int m0 = blockIdx.y * 64;
    int n0 = blockIdx.x * 64;
    int tx = tid & 15, ty = tid >> 4;

    int arow = tid >> 2;          // 0..63
    int akq  = (tid & 3) << 2;    // 0/4/8/12
    int brow = tid >> 4;          // 0..15
    int bcq  = (tid & 15) << 2;   // 0..60
    const float* Aptr = A + (long long)(m0 + arow) * K + akq;

    float acc[4][4] = {};
    for (int k0 = 0; k0 < K; k0 += 16) {
        float4 a4 = *(const float4*)(Aptr + k0);
        As[akq + 0][arow] = a4.x; As[akq + 1][arow] = a4.y;
        As[akq + 2][arow] = a4.z; As[akq + 3][arow] = a4.w;
        int col = n0 + bcq;
        float4 b4 = make_float4(0.f, 0.f, 0.f, 0.f);
        if (col < Ncols) b4 = *(const float4*)(Bp + (long long)(k0 + brow) * Ncols + col);
        *(float4*)&Bs[brow][bcq] = b4;
        __syncthreads();
        #pragma unroll
        for (int k = 0; k < 16; k++) {
            float4 av = *(const float4*)&As[k][ty << 2];
            float4 bv = *(const float4*)&Bs[k][tx << 2];
            acc[0][0] += av.x * bv.x; acc[0][1] += av.x * bv.y; acc[0][2] += av.x * bv.z; acc[0][3] += av.x * bv.w;
            acc[1][0] += av.y * bv.x; acc[1][1] += av.y * bv.y; acc[1][2] += av.y * bv.z; acc[1][3] += av.y * bv.w;
            acc[2][0] += av.z * bv.x; acc[2][1] += av.z * bv.y; acc[2][2] += av.z * bv.z; acc[2][3] += av.z * bv.w;
            acc[3][0] += av.w * bv.x; acc[3][1] += av.w * bv.y; acc[3][2] += av.w * bv.z; acc[3][3] += av.w * bv.w;
        }
        __syncthreads();
    }
    #pragma unroll
    for (int i = 0; i < 4; i++) {
        int row = m0 + (ty << 2) + i;
        float al = alpha[row], be = beta[row];
        #pragma unroll
        for (int j = 0; j < 4; j++) {
            int col = n0 + (tx << 2) + j;
            if (col < Ncols) Cp[(long long)row * Ncols + col] = acc[i][j] * al + be;
        }
    }
}

// --------------------- 2: depthwise 3x3 conv + affine -----------------------
__global__ void dwconv_kernel(const float* __restrict__ Wvl, const float* __restrict__ bvl,
                              const float* __restrict__ svl, const float* __restrict__ tvl)
{
    long long i = (long long)blockIdx.x * 256 + threadIdx.x;
    const long long total = (long long)NB * DH * NTOK;
    if (i >= total) return;
    int n  = (int)(i % NTOK);
    long long t = i / NTOK;
    int ch = (int)(t % DH);
    int b  = (int)(t / DH);
    int y = n / RR, x = n - y * RR;
    const float* vp = d_qkv + (long long)b * QKVOC * NTOK + (long long)(512 + ch) * NTOK;
    const float* wp = Wvl + ch * 9;
    float s = 0.f;
    #pragma unroll
    for (int ky = 0; ky < 3; ky++) {
        int yy = y + ky - 1;
        if (yy < 0 || yy >= RR) continue;
        #pragma unroll
        for (int kx = 0; kx < 3; kx++) {
            int xx = x + kx - 1;
            if (xx < 0 || xx >= RR) continue;
            s += vp[yy * RR + xx] * wp[ky * 3 + kx];
        }
    }
    d_vl[i] = (s + bvl[ch]) * svl[ch] + tvl[ch];
}

// ------------------------------ 3: sumV -------------------------------------
__global__ void sumv_kernel()
{
    int gw   = (blockIdx.x * blockDim.x + threadIdx.x) >> 5;  // global warp
    int lane = threadIdx.x & 31;
    if (gw >= NB * DH) return;
    int b = gw >> 10, ch = gw & 1023;
    const float* row = d_qkv + (long long)b * QKVOC * NTOK + (long long)(512 + ch) * NTOK;
    float s = 0.f;
    for (int m = lane; m < NTOK; m += 32) s += row[m];
    #pragma unroll
    for (int off = 16; off; off >>= 1) s += __shfl_xor_sync(0xffffffffu, s, off);
    if (lane == 0) d_sumV[gw] = s;
}

// --------------------- 4: attention logits + th1 mix ------------------------
// Tile: 32(n) x 32(m) per block, all 8 heads. grid(25,25,32)
__global__ void __launch_bounds__(256) attn_logits(
    const float* __restrict__ th1w, const float* __restrict__ th1b,
    const int* __restrict__ idxs)
{
    __shared__ float qs[128][32];
    __shared__ float ks[128][32];
    __shared__ float s_th1[64];
    __shared__ float s_th1b[8];

    int tid = threadIdx.x;
    int b   = blockIdx.z;
    int n0  = blockIdx.y * 32;
    int m0  = blockIdx.x * 32;
    const float* qb = d_qkv + (long long)b * QKVOC * NTOK;       // rows 0..255 = q
    const float* kb = qb + 256 * NTOK;                           // rows 256..511 = k

    if (tid < 64) s_th1[tid] = th1w[tid] * SCALE;
    if (tid < 8)  s_th1b[tid] = th1b[tid];

    int m  = tid & 31;
    int nb = (tid >> 5) << 2;   // 8 warps * 4 = 32 rows
    float acc[8][4] = {};

    #pragma unroll
    for (int cb = 0; cb < 2; cb++) {
        __syncthreads();
        for (int i = tid; i < 128 * 32; i += 256) {
            int row = i >> 5, col = i & 31;
            int gr  = cb * 128 + row;
            qs[row][col] = (n0 + col < NTOK) ? qb[gr * NTOK + n0 + col] : 0.f;
            ks[row][col] = (m0 + col < NTOK) ? kb[gr * NTOK + m0 + col] : 0.f;
        }
        __syncthreads();
        #pragma unroll
        for (int hl = 0; hl < 4; hl++) {
            int h = cb * 4 + hl;
            #pragma unroll 8
            for (int kd = 0; kd < 32; kd++) {
                int c = hl * 32 + kd;
                float  kv = ks[c][m];
                float4 q4 = *(const float4*)&qs[c][nb];
                acc[h][0] += q4.x * kv;
                acc[h][1] += q4.y * kv;
                acc[h][2] += q4.z * kv;
                acc[h][3] += q4.w * kv;
            }
        }
    }

    int mm  = m0 + m;
    bool mok = (mm < NTOK);
    int idxv[4];
    #pragma unroll
    for (int j = 0; j < 4; j++) {
        int nn = n0 + nb + j;
        idxv[j] = (mok && nn < NTOK) ? idxs[nn * NTOK + mm] : 0;
    }

    #pragma unroll
    for (int g = 0; g < HH; g++) {
        float tb = s_th1b[g];
        #pragma unroll
        for (int j = 0; j < 4; j++) {
            int nn = n0 + nb + j;
            if (mok && nn < NTOK) {
                float v = tb;
                #pragma unroll
                for (int h = 0; h < HH; h++) v += s_th1[g * 8 + h] * acc[h][j];
                v += d_abmix[g * NTOK + idxv[j]];
                d_L[(((long long)(b * HH + g)) * NTOK + nn) * NTOK + mm] = v;
            }
        }
    }
}

// ------------------- 5: softmax per head + th2 mix (in place) ---------------
// grid(784, 32); 8 warps, warp w handles head w.
__global__ void __launch_bounds__(256) softmax_mix(const float* __restrict__ th2w)
{
    __shared__ float P[HH][NTOK];
    __shared__ float s_th2[64];

    int n   = blockIdx.x;
    int b   = blockIdx.y;
    int tid = threadIdx.x;
    int warp = tid >> 5, lane = tid & 31;
    float* Lrow = d_L + (((long long)b * HH) * NTOK + n) * NTOK;
    const long long hstride = (long long)NTOK * NTOK;

    if (tid < 64) s_th2[tid] = th2w[tid];

    const float* src = Lrow + (long long)warp * hstride;
    float vals[25];
    float mx = -1e30f;
    #pragma unroll
    for (int i = 0; i < 25; i++) {
        int m = lane + i * 32;
        vals[i] = (m < NTOK) ? src[m] : -1e30f;
        mx = fmaxf(mx, vals[i]);
    }
    #pragma unroll
    for (int off = 16; off; off >>= 1) mx = fmaxf(mx, __shfl_xor_sync(0xffffffffu, mx, off));
    float sum = 0.f;
    #pragma unroll
    for (int i = 0; i < 25; i++) {
        float p = __expf(vals[i] - mx);
        vals[i] = p;
        sum += p;
    }
    #pragma unroll
    for (int off = 16; off; off >>= 1) sum += __shfl_xor_sync(0xffffffffu, sum, off);
    float inv = 1.f / sum;
    #pragma unroll
    for (int i = 0; i < 25; i++) {
        int m = lane + i * 32;
        if (m < NTOK) P[warp][m] = vals[i] * inv;
    }
    __syncthreads();

    for (int m = tid; m < NTOK; m += 256) {
        float p[8];
        #pragma unroll
        for (int h = 0; h < 8; h++) p[h] = P[h][m];
        #pragma unroll
        for (int g = 0; g < 8; g++) {
            float o = 0.f;
            #pragma unroll
            for (int h = 0; h < 8; h++) o += s_th2[g * 8 + h] * p[h];
            Lrow[(long long)g * hstride + m] = o;
        }
    }
}

// ---------- 6: NT GEMM  o = v @ attn2^T  + th2_b*sumV + vl, ReLU -------------
// grid(13, 2, 256): z = b*8+g, y = d-tile(64), x = n-tile(64). K=784 (49x16).
__global__ void __launch_bounds__(256) gemm_av(const float* __restrict__ th2b)
{
    __shared__ float As[16][68];
    __shared__ float Bs[16][68];
    int tid = threadIdx.x;
    int bg = blockIdx.z;
    int b  = bg >> 3, g = bg & 7;
    const float* Ap = d_qkv + (long long)b * QKVOC * NTOK + (long long)(512 + g * DDIM) * NTOK; // [128][784]
    const float* Bp = d_L + (long long)bg * NTOK * NTOK;                                        // [784][784]
    int m0 = blockIdx.y * 64;   // d
    int n0 = blockIdx.x * 64;   // n
    int tx = tid & 15, ty = tid >> 4;

    int lrow = tid >> 2;          // 0..63
    int lkq  = (tid & 3) << 2;    // 0/4/8/12

    float acc[4][4] = {};
    for (int k0 = 0; k0 < NTOK; k0 += 16) {
        float4 a4 = *(const float4*)(Ap + (long long)(m0 + lrow) * NTOK + k0 + lkq);
        As[lkq + 0][lrow] = a4.x; As[lkq + 1][lrow] = a4.y;
        As[lkq + 2][lrow] = a4.z; As[lkq + 3][lrow] = a4.w;
        int nrow = n0 + lrow;
        float4 b4 = make_float4(0.f, 0.f, 0.f, 0.f);
        if (nrow < NTOK) b4 = *(const float4*)(Bp + (long long)nrow * NTOK + k0 + lkq);
        Bs[lkq + 0][lrow] = b4.x; Bs[lkq + 1][lrow] = b4.y;
        Bs[lkq + 2][lrow] = b4.z; Bs[lkq + 3][lrow] = b4.w;
        __syncthreads();
        #pragma unroll
        for (int k = 0; k < 16; k++) {
            float4 av = *(const float4*)&As[k][ty << 2];
            float4 bv = *(const float4*)&Bs[k][tx << 2];
            acc[0][0] += av.x * bv.x; acc[0][1] += av.x * bv.y; acc[0][2] += av.x * bv.z; acc[0][3] += av.x * bv.w;
            acc[1][0] += av.y * bv.x; acc[1][1] += av.y * bv.y; acc[1][2] += av.y * bv.z; acc[1][3] += av.y * bv.w;
            acc[2][0] += av.z * bv.x; acc[2][1] += av.z * bv.y; acc[2][2] += av.z * bv.z; acc[2][3] += av.z * bv.w;
            acc[3][0] += av.w * bv.x; acc[3][1] += av.w * bv.y; acc[3][2] += av.w * bv.z; acc[3][3] += av.w * bv.w;
        }
        __syncthreads();
    }

    float tb = th2b[g];
    #pragma unroll
    for (int i = 0; i < 4; i++) {
        int dd = m0 + (ty << 2) + i;
        int ch = g * DDIM + dd;
        float base = tb * d_sumV[b * DH + ch];
        const float* vlrow = d_vl   + ((long long)b * DH + ch) * NTOK;
        float*       orow  = d_obuf + ((long long)b * DH + ch) * NTOK;
        #pragma unroll
        for (int j = 0; j < 4; j++) {
            int nn = n0 + (tx << 2) + j;
            if (nn < NTOK) {
                float v = acc[i][j] + base + vlrow[nn];
                orow[nn] = fmaxf(v, 0.f);
            }
        }
    }
}

// ------------------------------ launch --------------------------------------
extern "C" void kernel_launch(void* const* d_in, const int* in_sizes, int n_in,
                              void* d_out, int out_size)
{
    const float* x    = (const float*)d_in[0];
    const float* Wq   = (const float*)d_in[1];
    const float* bq   = (const float*)d_in[2];
    const float* sq   = (const float*)d_in[3];
    const float* tq   = (const float*)d_in[4];
    const float* Wk   = (const float*)d_in[5];
    const float* bk   = (const float*)d_in[6];
    const float* sk   = (const float*)d_in[7];
    const float* tk   = (const float*)d_in[8];
    const float* Wv   = (const float*)d_in[9];
    const float* bv   = (const float*)d_in[10];
    const float* sv   = (const float*)d_in[11];
    const float* tv   = (const float*)d_in[12];
    const float* Wvl  = (const float*)d_in[13];
    const float* bvl  = (const float*)d_in[14];
    const float* svl  = (const float*)d_in[15];
    const float* tvl  = (const float*)d_in[16];
    const float* th1w = (const float*)d_in[17];
    const float* th1b = (const float*)d_in[18];
    const float* th2w = (const float*)d_in[19];
    const float* th2b = (const float*)d_in[20];
    /* ab = d_in[21] used in pack */
    const float* ab   = (const float*)d_in[21];
    const float* Wp   = (const float*)d_in[22];
    const float* bp   = (const float*)d_in[23];
    const float* sp   = (const float*)d_in[24];
    const float* tp   = (const float*)d_in[25];
    const int*   idxs = (const int*)d_in[26];
    float* out = (float*)d_out;

    float *p_Wpack, *p_alpha1, *p_beta1, *p_alphaP, *p_betaP, *p_qkv, *p_obuf;
    cudaGetSymbolAddress((void**)&p_Wpack,  d_Wpack);
    cudaGetSymbolAddress((void**)&p_alpha1, d_alpha1);
    cudaGetSymbolAddress((void**)&p_beta1,  d_beta1);
    cudaGetSymbolAddress((void**)&p_alphaP, d_alphaP);
    cudaGetSymbolAddress((void**)&p_betaP,  d_betaP);
    cudaGetSymbolAddress((void**)&p_qkv,    d_qkv);
    cudaGetSymbolAddress((void**)&p_obuf,   d_obuf);

    // 0: pack weights / affines / abmix
    pack_params<<<(QKVOC * CDIM + 255) / 256, 256>>>(
        Wq, bq, sq, tq, Wk, bk, sk, tk, Wv, bv, sv, tv, bp, sp, tp, th1w, ab);

    // 1: fused QKV projection  (M=1536, N=784, K=384, batch 32)
    gemm_nn_affine<<<dim3(13, 24, NB), 256>>>(
        p_Wpack, x, (long long)CDIM * NTOK,
        p_qkv, (long long)QKVOC * NTOK,
        p_alpha1, p_beta1, QKVOC, NTOK, CDIM);

    // 2: depthwise 3x3 + affine on v
    {
        long long total = (long long)NB * DH * NTOK;
        dwconv_kernel<<<(unsigned)((total + 255) / 256), 256>>>(Wvl, bvl, svl, tvl);
    }

    // 3: sumV (one warp per (b,ch))
    sumv_kernel<<<(NB * DH * 32 + 255) / 256, 256>>>();

    // 4: logits + th1 mix
    attn_logits<<<dim3(25, 25, NB), 256>>>(th1w, th1b, idxs);

    // 5: softmax + th2 mix (in place on d_L)
    softmax_mix<<<dim3(NTOK, NB), 256>>>(th2w);

    // 6: attn @ v + th2_b*sumV + vl, ReLU
    gemm_av<<<dim3(13, 2, NB * HH), 256>>>(th2b);

    // 7: output projection  (M=384, N=784, K=1024, batch 32)
    gemm_nn_affine<<<dim3(13, 6, NB), 256>>>(
        Wp, p_obuf, (long long)DH * NTOK,
        out, (long long)CDIM * NTOK,
        p_alphaP, p_betaP, CDIM, NTOK, DH);
}

// round 10
// speedup vs baseline: 1.0016x; 1.0016x over previous
#include <cuda_runtime.h>
#include <cuda_bf16.h>
#include <math.h>

// ---------------------------------------------------------------------------
// Attention4D: B=32, DIM=384, R=28 (N=784), H=8, KD=32, D=128, DH=1024
// Pipeline:
//   0. pack:   Wqkv -> d_Wpack[1536x384], affine (alpha,beta), abmix = th1 @ ab
//   1. gemm_nn: qkv[b] = Wpack @ x[b]  (epilogue: *alpha + beta)     [32x1536x784]
//   2. dwconv:  vl = affine(dw3x3(v) + bvl)                          [32x1024x784]
//   3. sumv:    sumV[b,ch] = sum_m v[b,ch,m]
//   4. logits:  L[b,g,n,m] = sum_h th1[g,h]*SCALE*(q_h . k_h) + abmix[g,idx] + th1_b[g]
//   5. softmax_mix: per (b,n): softmax over m per head, then th2 8x8 mix, in place
//   6. gemm_av: o[b,g*128+d,n] = sum_m attn2 * v  (+ th2_b*sumV + vl, ReLU)
//   7. gemm_nn: out[b] = Wp @ o[b]  (epilogue: *alphaP + betaP)
// ---------------------------------------------------------------------------

#define NB    32
#define CDIM  384
#define RR    28
#define NTOK  784          // 28*28
#define HH    8
#define KDHD  32
#define DDIM  128
#define DH    1024
#define QKVOC 1536
#define SCALE 0.17677669529663689f   // 32^-0.5

// ------------------------- scratch (device globals) -------------------------
__device__ float d_Wpack [QKVOC * CDIM];
__device__ float d_alpha1[QKVOC];
__device__ float d_beta1 [QKVOC];
__device__ float d_alphaP[CDIM];
__device__ float d_betaP [CDIM];
__device__ float d_abmix [HH * NTOK];
__device__ float d_qkv [(long long)NB * QKVOC * NTOK];       // 154 MB
__device__ float d_L   [(long long)NB * HH * NTOK * NTOK];   // 629 MB
__device__ float d_vl  [(long long)NB * DH * NTOK];          // 103 MB
__device__ float d_obuf[(long long)NB * DH * NTOK];          // 103 MB
__device__ float d_sumV[NB * DH];

// ------------------------------ 0: pack ------------------------------------
__global__ void pack_params(const float* __restrict__ Wq, const float* __restrict__ bq,
                            const float* __restrict__ sq, const float* __restrict__ tq,
                            const float* __restrict__ Wk, const float* __restrict__ bk,
                            const float* __restrict__ sk, const float* __restrict__ tk,
                            const float* __restrict__ Wv, const float* __restrict__ bv,
                            const float* __restrict__ sv, const float* __restrict__ tv,
                            const float* __restrict__ bp, const float* __restrict__ sp,
                            const float* __restrict__ tp,
                            const float* __restrict__ th1w, const float* __restrict__ ab)
{
    int idx = blockIdx.x * 256 + threadIdx.x;
    if (idx < QKVOC * CDIM) {
        int row = idx / CDIM, col = idx - row * CDIM;
        float w;
        if (row < 256)      w = Wq[row * CDIM + col];
        else if (row < 512) w = Wk[(row - 256) * CDIM + col];
        else                w = Wv[(row - 512) * CDIM + col];
        d_Wpack[idx] = w;
    }
    if (idx < QKVOC) {
        float s, b0, t;
        if (idx < 256)      { s = sq[idx];       b0 = bq[idx];       t = tq[idx]; }
        else if (idx < 512) { int r = idx - 256; s = sk[r]; b0 = bk[r]; t = tk[r]; }
        else                { int r = idx - 512; s = sv[r]; b0 = bv[r]; t = tv[r]; }
        d_alpha1[idx] = s;
        d_beta1[idx]  = b0 * s + t;
    }
    if (idx < CDIM) {
        d_alphaP[idx] = sp[idx];
        d_betaP[idx]  = bp[idx] * sp[idx] + tp[idx];
    }
    if (idx < HH * NTOK) {
        int g = idx / NTOK, p = idx - g * NTOK;
        float acc = 0.f;
        #pragma unroll
        for (int h = 0; h < HH; h++) acc += th1w[g * HH + h] * ab[h * NTOK + p];
        d_abmix[idx] = acc;
    }
}

// ------------------------- generic NN SGEMM + affine ------------------------
// C[b] = A @ B[b], A row-major [M,K], B row-major [K,Ncols]. M%64==0, K%16==0.
__global__ void __launch_bounds__(256) gemm_nn_affine(
    const float* __restrict__ A, const float* __restrict__ B, long long strideB,
    float* __restrict__ C, long long strideC,
    const float* __restrict__ alpha, const float* __restrict__ beta,
    int M, int Ncols, int K)
{
    __shared__ float As[16][68];
    __shared__ float Bs[16][64];
    int tid = threadIdx.x;
    int b   = blockIdx.z;
    const float* Bp = B + (long long)b * strideB;
    float*       Cp = C + (long long)b * strideC;
    int m0 = blockIdx.y * 64;
    int n0 = blockIdx.x * 64;
    int tx = tid & 15, ty = tid >> 4;

    int arow = tid >> 2;          // 0..63
    int akq  = (tid & 3) << 2;    // 0/4/8/12
    int brow = tid >> 4;          // 0..15
    int bcq  = (tid & 15) << 2;   // 0..60
    const float* Aptr = A + (long long)(m0 + arow) * K + akq;

    float acc[4][4] = {};
    for (int k0 = 0; k0 < K; k0 += 16) {
        float4 a4 = *(const float4*)(Aptr + k0);
        As[akq + 0][arow] = a4.x; As[akq + 1][arow] = a4.y;
        As[akq + 2][arow] = a4.z; As[akq + 3][arow] = a4.w;
        int col = n0 + bcq;
        float4 b4 = make_float4(0.f, 0.f, 0.f, 0.f);
        if (col < Ncols) b4 = *(const float4*)(Bp + (long long)(k0 + brow) * Ncols + col);
        *(float4*)&Bs[brow][bcq] = b4;
        __syncthreads();
        #pragma unroll
        for (int k = 0; k < 16; k++) {
            float4 av = *(const float4*)&As[k][ty << 2];
            float4 bv = *(const float4*)&Bs[k][tx << 2];
            acc[0][0] += av.x * bv.x; acc[0][1] += av.x * bv.y; acc[0][2] += av.x * bv.z; acc[0][3] += av.x * bv.w;
            acc[1][0] += av.y * bv.x; acc[1][1] += av.y * bv.y; acc[1][2] += av.y * bv.z; acc[1][3] += av.y * bv.w;
            acc[2][0] += av.z * bv.x; acc[2][1] += av.z * bv.y; acc[2][2] += av.z * bv.z; acc[2][3] += av.z * bv.w;
            acc[3][0] += av.w * bv.x; acc[3][1] += av.w * bv.y; acc[3][2] += av.w * bv.z; acc[3][3] += av.w * bv.w;
        }
        __syncthreads();
    }
    #pragma unroll
    for (int i = 0; i < 4; i++) {
        int row = m0 + (ty << 2) + i;
        float al = alpha[row], be = beta[row];
        #pragma unroll
        for (int j = 0; j < 4; j++) {
            int col = n0 + (tx << 2) + j;
            if (col < Ncols) Cp[(long long)row * Ncols + col] = acc[i][j] * al + be;
        }
    }
}

// --------------------- 2: depthwise 3x3 conv + affine -----------------------
__global__ void dwconv_kernel(const float* __restrict__ Wvl, const float* __restrict__ bvl,
                              const float* __restrict__ svl, const float* __restrict__ tvl)
{
    long long i = (long long)blockIdx.x * 256 + threadIdx.x;
    const long long total = (long long)NB * DH * NTOK;
    if (i >= total) return;
    int n  = (int)(i % NTOK);
    long long t = i / NTOK;
    int ch = (int)(t % DH);
    int b  = (int)(t / DH);
    int y = n / RR, x = n - y * RR;
    const float* vp = d_qkv + (long long)b * QKVOC * NTOK + (long long)(512 + ch) * NTOK;
    const float* wp = Wvl + ch * 9;
    float s = 0.f;
    #pragma unroll
    for (int ky = 0; ky < 3; ky++) {
        int yy = y + ky - 1;
        if (yy < 0 || yy >= RR) continue;
        #pragma unroll
        for (int kx = 0; kx < 3; kx++) {
            int xx = x + kx - 1;
            if (xx < 0 || xx >= RR) continue;
            s += vp[yy * RR + xx] * wp[ky * 3 + kx];
        }
    }
    d_vl[i] = (s + bvl[ch]) * svl[ch] + tvl[ch];
}

// ------------------------------ 3: sumV -------------------------------------
__global__ void sumv_kernel()
{
    int gw   = (blockIdx.x * blockDim.x + threadIdx.x) >> 5;  // global warp
    int lane = threadIdx.x & 31;
    if (gw >= NB * DH) return;
    int b = gw >> 10, ch = gw & 1023;
    const float* row = d_qkv + (long long)b * QKVOC * NTOK + (long long)(512 + ch) * NTOK;
    float s = 0.f;
    for (int m = lane; m < NTOK; m += 32) s += row[m];
    #pragma unroll
    for (int off = 16; off; off >>= 1) s += __shfl_xor_sync(0xffffffffu, s, off);
    if (lane == 0) d_sumV[gw] = s;
}

// --------------------- 4: attention logits + th1 mix ------------------------
// Tile: 32(n) x 32(m) per block, all 8 heads. grid(25,25,32)
__global__ void __launch_bounds__(256) attn_logits(
    const float* __restrict__ th1w, const float* __restrict__ th1b,
    const int* __restrict__ idxs)
{
    __shared__ float qs[128][32];
    __shared__ float ks[128][32];
    __shared__ float s_th1[64];
    __shared__ float s_th1b[8];

    int tid = threadIdx.x;
    int b   = blockIdx.z;
    int n0  = blockIdx.y * 32;
    int m0  = blockIdx.x * 32;
    const float* qb = d_qkv + (long long)b * QKVOC * NTOK;       // rows 0..255 = q
    const float* kb = qb + 256 * NTOK;                           // rows 256..511 = k

    if (tid < 64) s_th1[tid] = th1w[tid] * SCALE;
    if (tid < 8)  s_th1b[tid] = th1b[tid];

    int m  = tid & 31;
    int nb = (tid >> 5) << 2;   // 8 warps * 4 = 32 rows
    float acc[8][4] = {};

    #pragma unroll
    for (int cb = 0; cb < 2; cb++) {
        __syncthreads();
        for (int i = tid; i < 128 * 32; i += 256) {
            int row = i >> 5, col = i & 31;
            int gr  = cb * 128 + row;
            qs[row][col] = (n0 + col < NTOK) ? qb[gr * NTOK + n0 + col] : 0.f;
            ks[row][col] = (m0 + col < NTOK) ? kb[gr * NTOK + m0 + col] : 0.f;
        }
        __syncthreads();
        #pragma unroll
        for (int hl = 0; hl < 4; hl++) {
            int h = cb * 4 + hl;
            #pragma unroll 8
            for (int kd = 0; kd < 32; kd++) {
                int c = hl * 32 + kd;
                float  kv = ks[c][m];
                float4 q4 = *(const float4*)&qs[c][nb];
                acc[h][0] += q4.x * kv;
                acc[h][1] += q4.y * kv;
                acc[h][2] += q4.z * kv;
                acc[h][3] += q4.w * kv;
            }
        }
    }

    int mm  = m0 + m;
    bool mok = (mm < NTOK);
    int idxv[4];
    #pragma unroll
    for (int j = 0; j < 4; j++) {
        int nn = n0 + nb + j;
        idxv[j] = (mok && nn < NTOK) ? idxs[nn * NTOK + mm] : 0;
    }

    #pragma unroll
    for (int g = 0; g < HH; g++) {
        float tb = s_th1b[g];
        #pragma unroll
        for (int j = 0; j < 4; j++) {
            int nn = n0 + nb + j;
            if (mok && nn < NTOK) {
                float v = tb;
                #pragma unroll
                for (int h = 0; h < HH; h++) v += s_th1[g * 8 + h] * acc[h][j];
                v += d_abmix[g * NTOK + idxv[j]];
                d_L[(((long long)(b * HH + g)) * NTOK + nn) * NTOK + mm] = v;
            }
        }
    }
}

// ------------------- 5: softmax per head + th2 mix (in place) ---------------
// grid(784, 32); 8 warps, warp w handles head w.
__global__ void __launch_bounds__(256) softmax_mix(const float* __restrict__ th2w)
{
    __shared__ float P[HH][NTOK];
    __shared__ float s_th2[64];

    int n   = blockIdx.x;
    int b   = blockIdx.y;
    int tid = threadIdx.x;
    int warp = tid >> 5, lane = tid & 31;
    float* Lrow = d_L + (((long long)b * HH) * NTOK + n) * NTOK;
    const long long hstride = (long long)NTOK * NTOK;

    if (tid < 64) s_th2[tid] = th2w[tid];

    const float* src = Lrow + (long long)warp * hstride;
    float vals[25];
    float mx = -1e30f;
    #pragma unroll
    for (int i = 0; i < 25; i++) {
        int m = lane + i * 32;
        vals[i] = (m < NTOK) ? src[m] : -1e30f;
        mx = fmaxf(mx, vals[i]);
    }
    #pragma unroll
    for (int off = 16; off; off >>= 1) mx = fmaxf(mx, __shfl_xor_sync(0xffffffffu, mx, off));
    float sum = 0.f;
    #pragma unroll
    for (int i = 0; i < 25; i++) {
        float p = __expf(vals[i] - mx);
        vals[i] = p;
        sum += p;
    }
    #pragma unroll
    for (int off = 16; off; off >>= 1) sum += __shfl_xor_sync(0xffffffffu, sum, off);
    float inv = 1.f / sum;
    #pragma unroll
    for (int i = 0; i < 25; i++) {
        int m = lane + i * 32;
        if (m < NTOK) P[warp][m] = vals[i] * inv;
    }
    __syncthreads();

    for (int m = tid; m < NTOK; m += 256) {
        float p[8];
        #pragma unroll
        for (int h = 0; h < 8; h++) p[h] = P[h][m];
        #pragma unroll
        for (int g = 0; g < 8; g++) {
            float o = 0.f;
            #pragma unroll
            for (int h = 0; h < 8; h++) o += s_th2[g * 8 + h] * p[h];
            Lrow[(long long)g * hstride + m] = o;
        }
    }
}

// ---------- 6: NT GEMM  o = v @ attn2^T  + th2_b*sumV + vl, ReLU -------------
// grid(13, 2, 256): z = b*8+g, y = d-tile(64), x = n-tile(64). K=784 (49x16).
__global__ void __launch_bounds__(256) gemm_av(const float* __restrict__ th2b)
{
    __shared__ float As[16][68];
    __shared__ float Bs[16][68];
    int tid = threadIdx.x;
    int bg = blockIdx.z;
    int b  = bg >> 3, g = bg & 7;
    const float* Ap = d_qkv + (long long)b * QKVOC * NTOK + (long long)(512 + g * DDIM) * NTOK; // [128][784]
    const float* Bp = d_L + (long long)bg * NTOK * NTOK;                                        // [784][784]
    int m0 = blockIdx.y * 64;   // d
    int n0 = blockIdx.x * 64;   // n
    int tx = tid & 15, ty = tid >> 4;

    int lrow = tid >> 2;          // 0..63
    int lkq  = (tid & 3) << 2;    // 0/4/8/12

    float acc[4][4] = {};
    for (int k0 = 0; k0 < NTOK; k0 += 16) {
        float4 a4 = *(const float4*)(Ap + (long long)(m0 + lrow) * NTOK + k0 + lkq);
        As[lkq + 0][lrow] = a4.x; As[lkq + 1][lrow] = a4.y;
        As[lkq + 2][lrow] = a4.z; As[lkq + 3][lrow] = a4.w;
        int nrow = n0 + lrow;
        float4 b4 = make_float4(0.f, 0.f, 0.f, 0.f);
        if (nrow < NTOK) b4 = *(const float4*)(Bp + (long long)nrow * NTOK + k0 + lkq);
        Bs[lkq + 0][lrow] = b4.x; Bs[lkq + 1][lrow] = b4.y;
        Bs[lkq + 2][lrow] = b4.z; Bs[lkq + 3][lrow] = b4.w;
        __syncthreads();
        #pragma unroll
        for (int k = 0; k < 16; k++) {
            float4 av = *(const float4*)&As[k][ty << 2];
            float4 bv = *(const float4*)&Bs[k][tx << 2];
            acc[0][0] += av.x * bv.x; acc[0][1] += av.x * bv.y; acc[0][2] += av.x * bv.z; acc[0][3] += av.x * bv.w;
            acc[1][0] += av.y * bv.x; acc[1][1] += av.y * bv.y; acc[1][2] += av.y * bv.z; acc[1][3] += av.y * bv.w;
            acc[2][0] += av.z * bv.x; acc[2][1] += av.z * bv.y; acc[2][2] += av.z * bv.z; acc[2][3] += av.z * bv.w;
            acc[3][0] += av.w * bv.x; acc[3][1] += av.w * bv.y; acc[3][2] += av.w * bv.z; acc[3][3] += av.w * bv.w;
        }
        __syncthreads();
    }

    float tb = th2b[g];
    #pragma unroll
    for (int i = 0; i < 4; i++) {
        int dd = m0 + (ty << 2) + i;
        int ch = g * DDIM + dd;
        float base = tb * d_sumV[b * DH + ch];
        const float* vlrow = d_vl   + ((long long)b * DH + ch) * NTOK;
        float*       orow  = d_obuf + ((long long)b * DH + ch) * NTOK;
        #pragma unroll
        for (int j = 0; j < 4; j++) {
            int nn = n0 + (tx << 2) + j;
            if (nn < NTOK) {
                float v = acc[i][j] + base + vlrow[nn];
                orow[nn] = fmaxf(v, 0.f);
            }
        }
    }
}

// ------------------------------ launch --------------------------------------
extern "C" void kernel_launch(void* const* d_in, const int* in_sizes, int n_in,
                              void* d_out, int out_size)
{
    const float* x    = (const float*)d_in[0];
    const float* Wq   = (const float*)d_in[1];
    const float* bq   = (const float*)d_in[2];
    const float* sq   = (const float*)d_in[3];
    const float* tq   = (const float*)d_in[4];
    const float* Wk   = (const float*)d_in[5];
    const float* bk   = (const float*)d_in[6];
    const float* sk   = (const float*)d_in[7];
    const float* tk   = (const float*)d_in[8];
    const float* Wv   = (const float*)d_in[9];
    const float* bv   = (const float*)d_in[10];
    const float* sv   = (const float*)d_in[11];
    const float* tv   = (const float*)d_in[12];
    const float* Wvl  = (const float*)d_in[13];
    const float* bvl  = (const float*)d_in[14];
    const float* svl  = (const float*)d_in[15];
    const float* tvl  = (const float*)d_in[16];
    const float* th1w = (const float*)d_in[17];
    const float* th1b = (const float*)d_in[18];
    const float* th2w = (const float*)d_in[19];
    const float* th2b = (const float*)d_in[20];
    /* ab = d_in[21] used in pack */
    const float* ab   = (const float*)d_in[21];
    const float* Wp   = (const float*)d_in[22];
    const float* bp   = (const float*)d_in[23];
    const float* sp   = (const float*)d_in[24];
    const float* tp   = (const float*)d_in[25];
    const int*   idxs = (const int*)d_in[26];
    float* out = (float*)d_out;

    float *p_Wpack, *p_alpha1, *p_beta1, *p_alphaP, *p_betaP, *p_qkv, *p_obuf;
    cudaGetSymbolAddress((void**)&p_Wpack,  d_Wpack);
    cudaGetSymbolAddress((void**)&p_alpha1, d_alpha1);
    cudaGetSymbolAddress((void**)&p_beta1,  d_beta1);
    cudaGetSymbolAddress((void**)&p_alphaP, d_alphaP);
    cudaGetSymbolAddress((void**)&p_betaP,  d_betaP);
    cudaGetSymbolAddress((void**)&p_qkv,    d_qkv);
    cudaGetSymbolAddress((void**)&p_obuf,   d_obuf);

    // 0: pack weights / affines / abmix
    pack_params<<<(QKVOC * CDIM + 255) / 256, 256>>>(
        Wq, bq, sq, tq, Wk, bk, sk, tk, Wv, bv, sv, tv, bp, sp, tp, th1w, ab);

    // 1: fused QKV projection  (M=1536, N=784, K=384, batch 32)
    gemm_nn_affine<<<dim3(13, 24, NB), 256>>>(
        p_Wpack, x, (long long)CDIM * NTOK,
        p_qkv, (long long)QKVOC * NTOK,
        p_alpha1, p_beta1, QKVOC, NTOK, CDIM);

    // 2: depthwise 3x3 + affine on v
    {
        long long total = (long long)NB * DH * NTOK;
        dwconv_kernel<<<(unsigned)((total + 255) / 256), 256>>>(Wvl, bvl, svl, tvl);
    }

    // 3: sumV (one warp per (b,ch))
    sumv_kernel<<<(NB * DH * 32 + 255) / 256, 256>>>();

    // 4: logits + th1 mix
    attn_logits<<<dim3(25, 25, NB), 256>>>(th1w, th1b, idxs);

    // 5: softmax + th2 mix (in place on d_L)
    softmax_mix<<<dim3(NTOK, NB), 256>>>(th2w);

    // 6: attn @ v + th2_b*sumV + vl, ReLU
    gemm_av<<<dim3(13, 2, NB * HH), 256>>>(th2b);

    // 7: output projection  (M=384, N=784, K=1024, batch 32)
    gemm_nn_affine<<<dim3(13, 6, NB), 256>>>(
        Wp, p_obuf, (long long)DH * NTOK,
        out, (long long)CDIM * NTOK,
        p_alphaP, p_betaP, CDIM, NTOK, DH);
}